// round 8
// baseline (speedup 1.0000x reference)
#include <cuda_runtime.h>
#include <cstdint>
#include <math.h>

#define TBL 512
#define THREADS 256
#define STAGE_P 512                    // patches per stage (8 KB)
#define STAGE_BYTES (STAGE_P * 16)
#define STAGES 5
#define GRID 512                       // 16 stages per CTA at B=4.19M, perfectly balanced

// Table of the scalar chain F(s), s in [0,1]:  entry i = { F(i/TBL), F((i+1)/TBL)-F(i/TBL) }
__device__ float2 d_tab[TBL];

// ---------------- Kernel 1: tabulate F(s) with accurate tanhf ----------------
__device__ __forceinline__ float eval_chain(float s,
                                            const float* __restrict__ Wl,
                                            const float* __restrict__ bl,
                                            const float* __restrict__ scale,
                                            const float* __restrict__ shift,
                                            const float* __restrict__ Wf,
                                            const float* __restrict__ bf)
{
    float x0 = s, x1 = 0.0f;
#pragma unroll
    for (int l = 0; l < 5; l++) {
        float y0 = tanhf(fmaf(x0, __ldg(Wl + 4 * l + 0), fmaf(x1, __ldg(Wl + 4 * l + 1), __ldg(bl + 2 * l + 0))));
        float y1 = tanhf(fmaf(x0, __ldg(Wl + 4 * l + 2), fmaf(x1, __ldg(Wl + 4 * l + 3), __ldg(bl + 2 * l + 1))));
        x0 = fmaf(y0, __ldg(scale + 2 * l + 0), __ldg(shift + 2 * l + 0));
        x1 = fmaf(y1, __ldg(scale + 2 * l + 1), __ldg(shift + 2 * l + 1));
    }
    return fmaf(x0, __ldg(Wf + 0), fmaf(x1, __ldg(Wf + 1), __ldg(bf)));
}

__global__ void tab_kernel(const float* __restrict__ Wl, const float* __restrict__ bl,
                           const float* __restrict__ scale, const float* __restrict__ shift,
                           const float* __restrict__ Wf, const float* __restrict__ bf)
{
    int j = blockIdx.x * blockDim.x + threadIdx.x;
    if (j >= TBL) return;
    const float inv = 1.0f / (float)TBL;
    float v0 = eval_chain((float)j * inv,       Wl, bl, scale, shift, Wf, bf);
    float v1 = eval_chain((float)(j + 1) * inv, Wl, bl, scale, shift, Wf, bf);
    d_tab[j] = make_float2(v0, v1 - v0);
}

// ---------------- mbarrier / bulk-copy helpers ----------------
__device__ __forceinline__ uint32_t s2u(const void* p) {
    return (uint32_t)__cvta_generic_to_shared(p);
}
__device__ __forceinline__ void mbar_init(uint32_t mbar, uint32_t count) {
    asm volatile("mbarrier.init.shared.b64 [%0], %1;" :: "r"(mbar), "r"(count) : "memory");
}
__device__ __forceinline__ void mbar_expect_tx(uint32_t mbar, uint32_t bytes) {
    asm volatile("mbarrier.arrive.expect_tx.shared.b64 _, [%0], %1;"
                 :: "r"(mbar), "r"(bytes) : "memory");
}
__device__ __forceinline__ void mbar_wait(uint32_t mbar, uint32_t phase) {
    asm volatile(
        "{\n\t"
        ".reg .pred P;\n\t"
        "WAIT_%=:\n\t"
        "mbarrier.try_wait.parity.acquire.cta.shared::cta.b64 P, [%0], %1, 0x989680;\n\t"
        "@!P bra WAIT_%=;\n\t"
        "}"
        :: "r"(mbar), "r"(phase) : "memory");
}
__device__ __forceinline__ void bulk_ld(uint32_t dst_smem, const void* src_gmem,
                                        uint32_t bytes, uint32_t mbar) {
    asm volatile(
        "cp.async.bulk.shared::cta.global.mbarrier::complete_tx::bytes [%0], [%1], %2, [%3];"
        :: "r"(dst_smem), "l"(src_gmem), "r"(bytes), "r"(mbar) : "memory");
}

// ---------------- Kernel 2: bulk-DMA pipelined streamer ----------------
__global__ __launch_bounds__(THREADS)
void fraud_kernel(const float4* __restrict__ data,
                  const float* __restrict__ Wc, const float* __restrict__ bc,
                  float* __restrict__ out, int B, int nstages)
{
    __shared__ __align__(16) float4 buf[STAGES][STAGE_P];   // 40 KB
    __shared__ float2 tab[TBL];                             // 4 KB
    __shared__ __align__(8) unsigned long long mbar_s[STAGES];

    const int tid = threadIdx.x;

    // table preload (1 float4 per thread for tid<256? TBL/2=256 float4s)
    if (tid < TBL / 2) ((float4*)tab)[tid] = ((const float4*)d_tab)[tid];

    // fold -log2(e) into conv weights:  s = 1/(1 + 2^(z'))
    const float NL2E = -1.4426950408889634f;
    const float wc0 = __ldg(Wc + 0) * NL2E, wc1 = __ldg(Wc + 1) * NL2E;
    const float wc2 = __ldg(Wc + 2) * NL2E, wc3 = __ldg(Wc + 3) * NL2E;
    const float bcv = __ldg(bc) * NL2E;

    if (tid == 0) {
#pragma unroll
        for (int s = 0; s < STAGES; s++) mbar_init(s2u(&mbar_s[s]), 1);
    }
    asm volatile("fence.proxy.async.shared::cta;" ::: "memory");
    __syncthreads();

    // ---- prologue: fill the pipeline ----
    if (tid == 0) {
#pragma unroll
        for (int k = 0; k < STAGES; k++) {
            const int st = blockIdx.x + k * GRID;
            if (st >= nstages) break;
            const size_t off = (size_t)st * STAGE_P;
            const int npatch = min(STAGE_P, B - (int)off);
            const uint32_t bytes = (uint32_t)npatch * 16u;
            const uint32_t mb = s2u(&mbar_s[k]);
            mbar_expect_tx(mb, bytes);
            bulk_ld(s2u(&buf[k][0]), data + off, bytes, mb);
        }
    }

    // ---- main loop ----
    for (int k = 0;; k++) {
        const int st = blockIdx.x + k * GRID;
        if (st >= nstages) break;
        const int slot = k % STAGES;
        const uint32_t phase = (uint32_t)(k / STAGES) & 1u;

        mbar_wait(s2u(&mbar_s[slot]), phase);

        const int base = st * STAGE_P;
#pragma unroll
        for (int j = 0; j < STAGE_P / THREADS; j++) {
            const int p = j * THREADS + tid;
            const int gi = base + p;
            if (gi < B) {
                const float4 v = buf[slot][p];
                const float zp = fmaf(v.x, wc0, fmaf(v.y, wc1,
                                 fmaf(v.z, wc2, fmaf(v.w, wc3, bcv))));
                float e;
                asm("ex2.approx.f32 %0, %1;" : "=f"(e) : "f"(zp));
                float s;
                asm("rcp.approx.f32 %0, %1;" : "=f"(s) : "f"(e + 1.0f));

                float t = s * (float)TBL;
                int idx = (int)t;
                idx = min(idx, TBL - 1);
                const float f = t - (float)idx;
                const float2 tv = tab[idx];
                __stcs(out + gi, fmaf(tv.y, f, tv.x));
            }
        }

        __syncthreads();   // everyone done reading buf[slot]

        // refill slot with stage k+STAGES
        const int nst = st + STAGES * GRID;
        if (nst < nstages && tid == 0) {
            const size_t off = (size_t)nst * STAGE_P;
            const int npatch = min(STAGE_P, B - (int)off);
            const uint32_t bytes = (uint32_t)npatch * 16u;
            const uint32_t mb = s2u(&mbar_s[slot]);
            mbar_expect_tx(mb, bytes);
            bulk_ld(s2u(&buf[slot][0]), data + off, bytes, mb);
        }
    }
}

extern "C" void kernel_launch(void* const* d_in, const int* in_sizes, int n_in,
                              void* d_out, int out_size)
{
    const float4* data  = (const float4*)d_in[0];
    const float*  Wc    = (const float*)d_in[1];
    const float*  bc    = (const float*)d_in[2];
    const float*  Wl    = (const float*)d_in[3];
    const float*  bl    = (const float*)d_in[4];
    const float*  scale = (const float*)d_in[5];
    const float*  shift = (const float*)d_in[6];
    const float*  Wf    = (const float*)d_in[7];
    const float*  bf    = (const float*)d_in[8];
    float* out = (float*)d_out;

    const int B = in_sizes[0] / 4;                       // 4 floats per patch
    const int nstages = (B + STAGE_P - 1) / STAGE_P;     // 8192 at B=4.19M

    tab_kernel<<<TBL / 128, 128>>>(Wl, bl, scale, shift, Wf, bf);
    fraud_kernel<<<GRID, THREADS>>>(data, Wc, bc, out, B, nstages);
}